// round 1
// baseline (speedup 1.0000x reference)
#include <cuda_runtime.h>

#define GAMMA     0.99f
#define B_ROWS    8192
#define T1        1025
#define NSCAN     1023      // number of recurrence steps
#define THREADS   128
#define ITEMS     8         // 128 * 8 = 1024 >= 1023

// Per-row partial sums of squared error (scratch; __device__ global, no alloc).
__device__ float g_partial[B_ROWS];

// One block per row. Parallel scan of the backward affine recurrence
//   y[t] = b[t] + a[t] * y[t+1],  y[1023] = Q[row][1024]
// in "scan order" s = 0..1022 with t = 1022 - s.
//   a[s] = GAMMA * c(1024 - s)
//   b[s] = rewards[1023 - s] + GAMMA * (eTQ[1024 - s] - c(1024 - s) * tQ[1024 - s])
//   c(k) = exp(min(tpp[k] - bpp[k], 0))
__global__ __launch_bounds__(THREADS)
void retrace_row_kernel(const float* __restrict__ Q,
                        const float* __restrict__ eTQ,
                        const float* __restrict__ tQ,
                        const float* __restrict__ rew,
                        const float* __restrict__ tpp,
                        const float* __restrict__ bpp)
{
    const int row = blockIdx.x;
    const long base = (long)row * T1;
    const float* __restrict__ q   = Q   + base;
    const float* __restrict__ eq  = eTQ + base;
    const float* __restrict__ tq  = tQ  + base;
    const float* __restrict__ rw  = rew + base;
    const float* __restrict__ tp  = tpp + base;
    const float* __restrict__ bp  = bpp + base;

    const int tid = threadIdx.x;

    // ---- Phase 1: load + per-thread affine composition ----
    float a[ITEMS], b[ITEMS];
    float A = 1.0f, Bc = 0.0f;   // composite affine of this thread's chunk (scan order)
    #pragma unroll
    for (int k = 0; k < ITEMS; k++) {
        const int s = tid * ITEMS + k;
        if (s < NSCAN) {
            const int i2 = 1024 - s;            // index t+2
            const float diff = tp[i2] - bp[i2];
            const float c  = __expf(fminf(diff, 0.0f));
            a[k] = GAMMA * c;
            b[k] = rw[1023 - s] + GAMMA * (eq[i2] - c * tq[i2]);
        } else {
            a[k] = 1.0f;                         // identity pad for s == 1023
            b[k] = 0.0f;
        }
        // compose f_s AFTER current composite:  (A,B) <- (a*A, a*B + b)
        Bc = fmaf(a[k], Bc, b[k]);
        A  = a[k] * A;
    }

    // ---- Block-wide inclusive scan over per-thread affines (Hillis-Steele) ----
    __shared__ float sA[THREADS];
    __shared__ float sB[THREADS];
    sA[tid] = A; sB[tid] = Bc;
    __syncthreads();
    #pragma unroll
    for (int off = 1; off < THREADS; off <<= 1) {
        float pa = 1.0f, pb = 0.0f;
        if (tid >= off) { pa = sA[tid - off]; pb = sB[tid - off]; }
        __syncthreads();
        if (tid >= off) {
            const float A1 = sA[tid], B1 = sB[tid];
            sA[tid] = A1 * pa;              // f_cur ∘ f_prev
            sB[tid] = fmaf(A1, pb, B1);
        }
        __syncthreads();
    }

    // ---- Phase 2: seed from exclusive prefix, replay chunk, accumulate error ----
    const float init = q[1024];
    float y = (tid == 0) ? init : fmaf(sA[tid - 1], init, sB[tid - 1]);

    float err = 0.0f;
    if (tid == 0) {                           // j = 1023 term: Q_ret[1023] = init
        const float d = q[1023] - init;
        err = d * d;
    }
    #pragma unroll
    for (int k = 0; k < ITEMS; k++) {
        const int s = tid * ITEMS + k;
        y = fmaf(a[k], y, b[k]);              // y = Q_ret[1022 - s]
        if (s < NSCAN) {
            const float d = q[1022 - s] - y;
            err = fmaf(d, d, err);
        }
    }

    // ---- Block reduction of err ----
    __shared__ float sred[THREADS];
    sred[tid] = err;
    __syncthreads();
    #pragma unroll
    for (int off = THREADS / 2; off > 0; off >>= 1) {
        if (tid < off) sred[tid] += sred[tid + off];
        __syncthreads();
    }
    if (tid == 0) g_partial[row] = sred[0];
}

// Deterministic final reduction: 8192 floats -> scalar mean.
__global__ void retrace_reduce_kernel(float* __restrict__ out)
{
    __shared__ double sd[256];
    double sum = 0.0;
    for (int i = threadIdx.x; i < B_ROWS; i += 256) sum += (double)g_partial[i];
    sd[threadIdx.x] = sum;
    __syncthreads();
    #pragma unroll
    for (int off = 128; off > 0; off >>= 1) {
        if (threadIdx.x < off) sd[threadIdx.x] += sd[threadIdx.x + off];
        __syncthreads();
    }
    if (threadIdx.x == 0)
        out[0] = (float)(sd[0] / ((double)B_ROWS * 1024.0));
}

extern "C" void kernel_launch(void* const* d_in, const int* in_sizes, int n_in,
                              void* d_out, int out_size)
{
    (void)in_sizes; (void)n_in; (void)out_size;
    const float* Q    = (const float*)d_in[0];
    const float* eTQ  = (const float*)d_in[1];
    const float* tQ   = (const float*)d_in[2];
    const float* rew  = (const float*)d_in[3];
    const float* tpp  = (const float*)d_in[4];
    const float* bpp  = (const float*)d_in[5];
    float* out = (float*)d_out;

    retrace_row_kernel<<<B_ROWS, THREADS>>>(Q, eTQ, tQ, rew, tpp, bpp);
    retrace_reduce_kernel<<<1, 256>>>(out);
}